// round 10
// baseline (speedup 1.0000x reference)
#include <cuda_runtime.h>
#include <cstdint>

#define EMBED   768
#define THREE_E 2304
#define HEADS   12
#define HDIM    64
#define SEQ     1024
#define BATCH   8
#define TOKENS  (BATCH*SEQ)

// QKV scratch: [8192 tokens][2304] fp32 (q | k | v, each 768 = 12 heads * 64)
__device__ float g_qkv[(size_t)TOKENS * THREE_E];

// ---------- packed f32x2 helpers (sm_100+) ----------
__device__ __forceinline__ unsigned long long pk2(float lo, float hi){
    unsigned long long r;
    asm("mov.b64 %0, {%1, %2};" : "=l"(r) : "f"(lo), "f"(hi));
    return r;
}
__device__ __forceinline__ unsigned long long dup2(float x){
    unsigned long long r;
    asm("mov.b64 %0, {%1, %1};" : "=l"(r) : "f"(x));
    return r;
}
__device__ __forceinline__ float2 up2(unsigned long long v){
    float2 r;
    asm("mov.b64 {%0, %1}, %2;" : "=f"(r.x), "=f"(r.y) : "l"(v));
    return r;
}
__device__ __forceinline__ void fma2(unsigned long long &d, unsigned long long a, unsigned long long b){
    asm("fma.rn.f32x2 %0, %1, %2, %0;" : "+l"(d) : "l"(a), "l"(b));
}

// ---------- mma helpers ----------
__device__ __forceinline__ uint32_t smem_u32(const void* p){
    uint32_t a;
    asm("{ .reg .u64 t; cvta.to.shared.u64 t, %1; cvt.u32.u64 %0, t; }" : "=r"(a) : "l"(p));
    return a;
}
__device__ __forceinline__ float tf32r(float x){
    uint32_t u;
    asm("cvt.rna.tf32.f32 %0, %1;" : "=r"(u) : "f"(x));
    return __uint_as_float(u);
}
__device__ __forceinline__ void ldsm4(uint32_t r[4], uint32_t addr){
    asm volatile("ldmatrix.sync.aligned.m8n8.x4.shared.b16 {%0,%1,%2,%3}, [%4];"
                 : "=r"(r[0]), "=r"(r[1]), "=r"(r[2]), "=r"(r[3]) : "r"(addr));
}
__device__ __forceinline__ void mma_tf32(float c[4], const uint32_t a[4], const uint32_t b[2]){
    asm volatile(
        "mma.sync.aligned.m16n8k8.row.col.f32.tf32.tf32.f32 "
        "{%0,%1,%2,%3}, {%4,%5,%6,%7}, {%8,%9}, {%0,%1,%2,%3};"
        : "+f"(c[0]), "+f"(c[1]), "+f"(c[2]), "+f"(c[3])
        : "r"(a[0]), "r"(a[1]), "r"(a[2]), "r"(a[3]), "r"(b[0]), "r"(b[1]));
}

// ============================================================
// Kernel 1: QKV GEMM (scalar f32x2 — known good, exact fp32)
// ============================================================
__global__ __launch_bounds__(256, 2)
void qkv_gemm(const float* __restrict__ X, const float* __restrict__ W,
              const float* __restrict__ bias){
    __shared__ float As[16][128];
    __shared__ float Bs[16][128];

    const int tid = threadIdx.x;
    const int bm = blockIdx.y * 128;
    const int bn = blockIdx.x * 128;
    const int tx = tid & 15;
    const int ty = tid >> 4;
    const int lr = tid >> 2;
    const int lc = (tid & 3) << 2;

    unsigned long long acc[8][4];
    #pragma unroll
    for (int i = 0; i < 8; i++)
        #pragma unroll
        for (int j = 0; j < 4; j++) acc[i][j] = 0ull;

    const float* Ap0 = X + (size_t)(bm + lr)      * EMBED + lc;
    const float* Ap1 = X + (size_t)(bm + lr + 64) * EMBED + lc;
    const float* Bp0 = W + (size_t)(bn + lr)      * EMBED + lc;
    const float* Bp1 = W + (size_t)(bn + lr + 64) * EMBED + lc;

    float4 pa0 = *(const float4*)Ap0;
    float4 pa1 = *(const float4*)Ap1;
    float4 pb0 = *(const float4*)Bp0;
    float4 pb1 = *(const float4*)Bp1;

    const int NKT = EMBED / 16;
    for (int kt = 0; kt < NKT; kt++){
        __syncthreads();
        {
            float a0[4] = {pa0.x, pa0.y, pa0.z, pa0.w};
            float a1[4] = {pa1.x, pa1.y, pa1.z, pa1.w};
            float b0[4] = {pb0.x, pb0.y, pb0.z, pb0.w};
            float b1[4] = {pb1.x, pb1.y, pb1.z, pb1.w};
            #pragma unroll
            for (int i = 0; i < 4; i++){
                As[lc + i][lr]      = a0[i];
                As[lc + i][lr + 64] = a1[i];
                Bs[lc + i][lr]      = b0[i];
                Bs[lc + i][lr + 64] = b1[i];
            }
        }
        __syncthreads();
        if (kt + 1 < NKT){
            pa0 = *(const float4*)(Ap0 + (kt + 1) * 16);
            pa1 = *(const float4*)(Ap1 + (kt + 1) * 16);
            pb0 = *(const float4*)(Bp0 + (kt + 1) * 16);
            pb1 = *(const float4*)(Bp1 + (kt + 1) * 16);
        }
        #pragma unroll
        for (int kk = 0; kk < 16; kk++){
            float4 a0 = *(const float4*)&As[kk][ty * 8];
            float4 a1 = *(const float4*)&As[kk][ty * 8 + 4];
            ulonglong2 b0 = *(const ulonglong2*)&Bs[kk][tx * 8];
            ulonglong2 b1 = *(const ulonglong2*)&Bs[kk][tx * 8 + 4];
            float av[8] = {a0.x, a0.y, a0.z, a0.w, a1.x, a1.y, a1.z, a1.w};
            #pragma unroll
            for (int i = 0; i < 8; i++){
                unsigned long long aa = dup2(av[i]);
                fma2(acc[i][0], aa, b0.x);
                fma2(acc[i][1], aa, b0.y);
                fma2(acc[i][2], aa, b1.x);
                fma2(acc[i][3], aa, b1.y);
            }
        }
    }

    float4 bs0 = *(const float4*)&bias[bn + tx * 8];
    float4 bs1 = *(const float4*)&bias[bn + tx * 8 + 4];
    #pragma unroll
    for (int i = 0; i < 8; i++){
        float2 c0 = up2(acc[i][0]), c1 = up2(acc[i][1]);
        float2 c2 = up2(acc[i][2]), c3 = up2(acc[i][3]);
        float4 o0 = make_float4(c0.x + bs0.x, c0.y + bs0.y, c1.x + bs0.z, c1.y + bs0.w);
        float4 o1 = make_float4(c2.x + bs1.x, c2.y + bs1.y, c3.x + bs1.z, c3.y + bs1.w);
        float* cp = g_qkv + (size_t)(bm + ty * 8 + i) * THREE_E + bn + tx * 8;
        *(float4*)cp       = o0;
        *(float4*)(cp + 4) = o1;
    }
}

// ============================================================
// Kernel 2: fused attention.
// Pass 1: Q held in REGISTERS (lane L owns Q[4 rows][2L,2L+1]),
//   broadcast per d-group via __shfl_sync (off the LDS crossbar).
//   K tiles 256x64 m-major Ks[256][68]; thread tile 4r x 8c
//   (cols = lane + 32i). Exact fp32 f32x2; floor(s/8) unchanged.
// Softmax: unchanged (tf32-rounded exp weights).
// Pass 2: tf32 mma, V DOUBLE-BUFFERED (1 barrier/kt).
// ============================================================
#define SSTR 1028
#define KSTR 68
#define VSTR 68

__global__ __launch_bounds__(256, 1)
void attn_kernel(float* __restrict__ out){
    extern __shared__ float sm[];
    float* Ss   = sm;                    // 32 * 1028
    float* Ks   = Ss + 32 * SSTR;        // 256 * 68 (m-major)
    float* rinv = Ks + 256 * KSTR;       // 32
    float* Vs0  = Ks;                    // alias: pass-2 V buf 0 (64 x 68)
    float* Vs1  = Ks + 64 * VSTR;        // alias: pass-2 V buf 1

    const int tid  = threadIdx.x;
    const int warp = tid >> 5;
    const int lane = tid & 31;
    const int bh   = blockIdx.x >> 5;
    const int row0 = (blockIdx.x & 31) * 32;
    const int b = bh / HEADS;
    const int h = bh % HEADS;

    const float* qbase = g_qkv + (size_t)(b * SEQ) * THREE_E + h * HDIM;
    const float* kbase = qbase + EMBED;
    const float* vbase = qbase + 2 * EMBED;

    // ---- Q into registers: qreg[r] = Q[row0 + 4*warp + r][2*lane .. 2*lane+1]
    const int r0 = warp * 4;
    unsigned long long qreg[4];
    #pragma unroll
    for (int r = 0; r < 4; r++){
        float2 t = *(const float2*)(qbase + (size_t)(row0 + r0 + r) * THREE_E + 2 * lane);
        qreg[r] = pk2(t.x, t.y);
    }

    // =========== pass 1: S = floor(Q K^T / 8), exact fp32 ===========
    #pragma unroll 1
    for (int kt = 0; kt < SEQ / 256; kt++){
        if (kt) __syncthreads();   // protect Ks overwrite vs previous compute
        // load K tile 256 x 64 (m-major, conflict-free float4 STS)
        #pragma unroll
        for (int it = 0; it < 16; it++){
            int idx = it * 256 + tid;
            int m = idx >> 4, dc = idx & 15;
            float4 v = *(const float4*)(kbase + (size_t)(kt * 256 + m) * THREE_E + dc * 4);
            *(float4*)&Ks[m * KSTR + dc * 4] = v;
        }
        __syncthreads();

        unsigned long long acc[4][8];
        #pragma unroll
        for (int r = 0; r < 4; r++)
            #pragma unroll
            for (int i = 0; i < 8; i++) acc[r][i] = 0ull;

        #pragma unroll
        for (int dg = 0; dg < 16; dg++){
            unsigned long long qa[4], qb[4];
            #pragma unroll
            for (int r = 0; r < 4; r++){
                qa[r] = __shfl_sync(0xffffffffu, qreg[r], 2 * dg);
                qb[r] = __shfl_sync(0xffffffffu, qreg[r], 2 * dg + 1);
            }
            #pragma unroll
            for (int i = 0; i < 8; i++){
                ulonglong2 kv = *(const ulonglong2*)&Ks[(lane + 32 * i) * KSTR + dg * 4];
                #pragma unroll
                for (int r = 0; r < 4; r++){
                    fma2(acc[r][i], qa[r], kv.x);
                    fma2(acc[r][i], qb[r], kv.y);
                }
            }
        }

        // horizontal add + floor + scalar store (conflict-free: col ≡ lane mod 32)
        #pragma unroll
        for (int r = 0; r < 4; r++){
            float* srow = &Ss[(r0 + r) * SSTR + kt * 256 + lane];
            #pragma unroll
            for (int i = 0; i < 8; i++){
                float2 t = up2(acc[r][i]);
                srow[32 * i] = floorf((t.x + t.y) * 0.125f);
            }
        }
    }
    __syncthreads();

    // ---- prefetch V tile 0 ----
    float4 vp[4];
    #pragma unroll
    for (int it = 0; it < 4; it++){
        int idx = it * 256 + tid;
        int m = idx >> 4, dc = idx & 15;
        vp[it] = *(const float4*)(vbase + (size_t)m * THREE_E + dc * 4);
    }

    // =========== softmax: exp stored tf32-rounded; 1/sum -> rinv ===========
    #pragma unroll
    for (int rr = 0; rr < 4; rr++){
        int r = warp * 4 + rr;
        float4* row4 = (float4*)&Ss[r * SSTR];
        float mx = -1e30f;
        #pragma unroll
        for (int i = 0; i < 8; i++){
            float4 v = row4[lane + i * 32];
            mx = fmaxf(mx, fmaxf(fmaxf(v.x, v.y), fmaxf(v.z, v.w)));
        }
        #pragma unroll
        for (int o = 16; o > 0; o >>= 1) mx = fmaxf(mx, __shfl_xor_sync(0xffffffffu, mx, o));
        float sum = 0.f;
        #pragma unroll
        for (int i = 0; i < 8; i++){
            float4 v = row4[lane + i * 32];
            v.x = tf32r(__expf(v.x - mx)); v.y = tf32r(__expf(v.y - mx));
            v.z = tf32r(__expf(v.z - mx)); v.w = tf32r(__expf(v.w - mx));
            sum += (v.x + v.y) + (v.z + v.w);
            row4[lane + i * 32] = v;
        }
        #pragma unroll
        for (int o = 16; o > 0; o >>= 1) sum += __shfl_xor_sync(0xffffffffu, sum, o);
        if (lane == 0) rinv[r] = 1.0f / sum;
    }

    // ---- prime pass 2: STS V tile 0 -> Vs0, prefetch tile 1 ----
    #pragma unroll
    for (int it = 0; it < 4; it++){
        int idx = it * 256 + tid;
        int m = idx >> 4, dc = idx & 15;
        float4 v = vp[it];
        v.x = tf32r(v.x); v.y = tf32r(v.y); v.z = tf32r(v.z); v.w = tf32r(v.w);
        *(float4*)&Vs0[m * VSTR + dc * 4] = v;
    }
    #pragma unroll
    for (int it = 0; it < 4; it++){
        int idx = it * 256 + tid;
        int m = idx >> 4, dc = idx & 15;
        vp[it] = *(const float4*)(vbase + (size_t)(64 + m) * THREE_E + dc * 4);
    }
    __syncthreads();   // Vs0 ready; softmax stores to Ss visible

    // =========== pass 2: C = E @ V via tf32 mma (double-buffered V) ===========
    const int mtile = warp & 1;
    const int nt0   = (warp >> 1) * 2;
    float C0[4] = {0.f,0.f,0.f,0.f}, C1[4] = {0.f,0.f,0.f,0.f};

    const uint32_t e_row  = (uint32_t)(mtile * 16 + (lane & 7) + ((lane >> 3) & 1) * 8);
    const uint32_t e_base = smem_u32(Ss) + e_row * (SSTR * 4) + (uint32_t)((lane >> 4) * 16);
    const int bm_ = lane & 3;
    const int bd_ = lane >> 2;
    const int v_off = bm_ * VSTR + nt0 * 8 + bd_;

    #pragma unroll 1
    for (int kt = 0; kt < 16; kt++){
        const float* cur = (kt & 1) ? Vs1 : Vs0;
        const float* vs_b0 = cur + v_off;

        const uint32_t e_kt = e_base + (uint32_t)(kt * 64 * 4);
        #pragma unroll
        for (int ks = 0; ks < 8; ks++){
            uint32_t ea[4];
            ldsm4(ea, e_kt + (uint32_t)(ks * 32));
            const float* vrow0 = vs_b0 + (8 * ks) * VSTR;
            const float* vrow1 = vrow0 + 4 * VSTR;
            uint32_t b0[2], b1[2];
            b0[0] = __float_as_uint(vrow0[0]);
            b0[1] = __float_as_uint(vrow1[0]);
            b1[0] = __float_as_uint(vrow0[8]);
            b1[1] = __float_as_uint(vrow1[8]);
            mma_tf32(C0, ea, b0);
            mma_tf32(C1, ea, b1);
        }

        if (kt < 15){
            // STS tile kt+1 into the buffer NOT being read this iteration
            float* nxt = (kt & 1) ? Vs0 : Vs1;
            #pragma unroll
            for (int it = 0; it < 4; it++){
                int idx = it * 256 + tid;
                int m = idx >> 4, dc = idx & 15;
                float4 v = vp[it];
                v.x = tf32r(v.x); v.y = tf32r(v.y); v.z = tf32r(v.z); v.w = tf32r(v.w);
                *(float4*)&nxt[m * VSTR + dc * 4] = v;
            }
            if (kt < 14){
                #pragma unroll
                for (int it = 0; it < 4; it++){
                    int idx = it * 256 + tid;
                    int m = idx >> 4, dc = idx & 15;
                    vp[it] = *(const float4*)(vbase + (size_t)((kt + 2) * 64 + m) * THREE_E + dc * 4);
                }
            }
        }
        __syncthreads();
    }

    // ---- epilogue ----
    {
        const int er0 = mtile * 16 + (lane >> 2);
        const int d0  = nt0 * 8 + 2 * (lane & 3);
        float i0 = rinv[er0], i1 = rinv[er0 + 8];
        float* op0 = out + (size_t)(bh * SEQ + row0 + er0) * HDIM + d0;
        float* op1 = op0 + 8 * HDIM;
        *(float2*)op0       = make_float2(C0[0] * i0, C0[1] * i0);
        *(float2*)(op0 + 8) = make_float2(C1[0] * i0, C1[1] * i0);
        *(float2*)op1       = make_float2(C0[2] * i1, C0[3] * i1);
        *(float2*)(op1 + 8) = make_float2(C1[2] * i1, C1[3] * i1);
    }
}

// ============================================================
// launch
// ============================================================
extern "C" void kernel_launch(void* const* d_in, const int* in_sizes, int n_in,
                              void* d_out, int out_size) {
    const float* x    = (const float*)d_in[0];   // [8,1024,768]
    const float* Wqkv = (const float*)d_in[1];   // [2304,768]
    const float* bqkv = (const float*)d_in[2];   // [2304]
    float* out = (float*)d_out;                  // [8,12,1024,64]

    const int attn_smem = (32 * SSTR + 256 * KSTR + 32) * (int)sizeof(float); // 201344 B
    cudaFuncSetAttribute(attn_kernel, cudaFuncAttributeMaxDynamicSharedMemorySize, attn_smem);

    dim3 g1(THREE_E / 128, TOKENS / 128);
    qkv_gemm<<<g1, 256>>>(x, Wqkv, bqkv);

    attn_kernel<<<BATCH * HEADS * (SEQ / 32), 256, attn_smem>>>(out);
}

// round 11
// speedup vs baseline: 1.1018x; 1.1018x over previous
#include <cuda_runtime.h>
#include <cuda_fp16.h>
#include <cstdint>

#define EMBED   768
#define THREE_E 2304
#define HEADS   12
#define HDIM    64
#define SEQ     1024
#define BATCH   8
#define TOKENS  (BATCH*SEQ)

// QKV scratch: [8192 tokens][2304] fp32 (q | k | v, each 768 = 12 heads * 64)
__device__ float g_qkv[(size_t)TOKENS * THREE_E];

// ---------- packed f32x2 helpers (sm_100+) ----------
__device__ __forceinline__ unsigned long long dup2(float x){
    unsigned long long r;
    asm("mov.b64 %0, {%1, %1};" : "=l"(r) : "f"(x));
    return r;
}
__device__ __forceinline__ float2 up2(unsigned long long v){
    float2 r;
    asm("mov.b64 {%0, %1}, %2;" : "=f"(r.x), "=f"(r.y) : "l"(v));
    return r;
}
__device__ __forceinline__ void fma2(unsigned long long &d, unsigned long long a, unsigned long long b){
    asm("fma.rn.f32x2 %0, %1, %2, %0;" : "+l"(d) : "l"(a), "l"(b));
}

// ---------- mma helpers ----------
__device__ __forceinline__ float tf32r(float x){
    uint32_t u;
    asm("cvt.rna.tf32.f32 %0, %1;" : "=r"(u) : "f"(x));
    return __uint_as_float(u);
}
__device__ __forceinline__ void mma_tf32(float c[4], const uint32_t a[4], const uint32_t b[2]){
    asm volatile(
        "mma.sync.aligned.m16n8k8.row.col.f32.tf32.tf32.f32 "
        "{%0,%1,%2,%3}, {%4,%5,%6,%7}, {%8,%9}, {%0,%1,%2,%3};"
        : "+f"(c[0]), "+f"(c[1]), "+f"(c[2]), "+f"(c[3])
        : "r"(a[0]), "r"(a[1]), "r"(a[2]), "r"(a[3]), "r"(b[0]), "r"(b[1]));
}

// ============================================================
// Kernel 1: QKV GEMM (scalar f32x2 — known good, exact fp32)
// ============================================================
__global__ __launch_bounds__(256, 2)
void qkv_gemm(const float* __restrict__ X, const float* __restrict__ W,
              const float* __restrict__ bias){
    __shared__ float As[16][128];
    __shared__ float Bs[16][128];

    const int tid = threadIdx.x;
    const int bm = blockIdx.y * 128;
    const int bn = blockIdx.x * 128;
    const int tx = tid & 15;
    const int ty = tid >> 4;
    const int lr = tid >> 2;
    const int lc = (tid & 3) << 2;

    unsigned long long acc[8][4];
    #pragma unroll
    for (int i = 0; i < 8; i++)
        #pragma unroll
        for (int j = 0; j < 4; j++) acc[i][j] = 0ull;

    const float* Ap0 = X + (size_t)(bm + lr)      * EMBED + lc;
    const float* Ap1 = X + (size_t)(bm + lr + 64) * EMBED + lc;
    const float* Bp0 = W + (size_t)(bn + lr)      * EMBED + lc;
    const float* Bp1 = W + (size_t)(bn + lr + 64) * EMBED + lc;

    float4 pa0 = *(const float4*)Ap0;
    float4 pa1 = *(const float4*)Ap1;
    float4 pb0 = *(const float4*)Bp0;
    float4 pb1 = *(const float4*)Bp1;

    const int NKT = EMBED / 16;
    for (int kt = 0; kt < NKT; kt++){
        __syncthreads();
        {
            float a0[4] = {pa0.x, pa0.y, pa0.z, pa0.w};
            float a1[4] = {pa1.x, pa1.y, pa1.z, pa1.w};
            float b0[4] = {pb0.x, pb0.y, pb0.z, pb0.w};
            float b1[4] = {pb1.x, pb1.y, pb1.z, pb1.w};
            #pragma unroll
            for (int i = 0; i < 4; i++){
                As[lc + i][lr]      = a0[i];
                As[lc + i][lr + 64] = a1[i];
                Bs[lc + i][lr]      = b0[i];
                Bs[lc + i][lr + 64] = b1[i];
            }
        }
        __syncthreads();
        if (kt + 1 < NKT){
            pa0 = *(const float4*)(Ap0 + (kt + 1) * 16);
            pa1 = *(const float4*)(Ap1 + (kt + 1) * 16);
            pb0 = *(const float4*)(Bp0 + (kt + 1) * 16);
            pb1 = *(const float4*)(Bp1 + (kt + 1) * 16);
        }
        #pragma unroll
        for (int kk = 0; kk < 16; kk++){
            float4 a0 = *(const float4*)&As[kk][ty * 8];
            float4 a1 = *(const float4*)&As[kk][ty * 8 + 4];
            ulonglong2 b0 = *(const ulonglong2*)&Bs[kk][tx * 8];
            ulonglong2 b1 = *(const ulonglong2*)&Bs[kk][tx * 8 + 4];
            float av[8] = {a0.x, a0.y, a0.z, a0.w, a1.x, a1.y, a1.z, a1.w};
            #pragma unroll
            for (int i = 0; i < 8; i++){
                unsigned long long aa = dup2(av[i]);
                fma2(acc[i][0], aa, b0.x);
                fma2(acc[i][1], aa, b0.y);
                fma2(acc[i][2], aa, b1.x);
                fma2(acc[i][3], aa, b1.y);
            }
        }
    }

    float4 bs0 = *(const float4*)&bias[bn + tx * 8];
    float4 bs1 = *(const float4*)&bias[bn + tx * 8 + 4];
    #pragma unroll
    for (int i = 0; i < 8; i++){
        float2 c0 = up2(acc[i][0]), c1 = up2(acc[i][1]);
        float2 c2 = up2(acc[i][2]), c3 = up2(acc[i][3]);
        float4 o0 = make_float4(c0.x + bs0.x, c0.y + bs0.y, c1.x + bs0.z, c1.y + bs0.w);
        float4 o1 = make_float4(c2.x + bs1.x, c2.y + bs1.y, c3.x + bs1.z, c3.y + bs1.w);
        float* cp = g_qkv + (size_t)(bm + ty * 8 + i) * THREE_E + bn + tx * 8;
        *(float4*)cp       = o0;
        *(float4*)(cp + 4) = o1;
    }
}

// ============================================================
// Kernel 2: fused attention, 2 CTAs/SM (fp16 score strip).
// Score strip Ss: fp16 [32][1034] — floored scores are small
//   integers (exact in fp16); exp-weights quantized (sum computed
//   from quantized values for error cancellation).
// Pass 1: K tiles 128x68 fp32; warp = 4 rows x 128 cols
//   (cols lane+32i); Q via broadcast LDS. Exact fp32 f32x2.
// Pass 2: tf32 mma; A-frags = 4 scalar LDH + cvt (fp16->fp32 is
//   exact); V path unchanged (fp32/tf32, double-buffered).
// ============================================================
#define SSTR2 1034          // fp16 elems per row (1024 + 10 pad; 517 words -> conflict-free)
#define QSTR  68
#define KSTR  68
#define VSTR  68
#define SS_BYTES  (32 * SSTR2 * 2)            // 66176
#define K_BYTES   (128 * KSTR * 4)            // 34816
#define ATTN_SMEM (SS_BYTES + K_BYTES + 128 + 32 * QSTR * 4)   // 109824

__global__ __launch_bounds__(256, 2)
void attn_kernel(float* __restrict__ out){
    extern __shared__ char smraw[];
    __half* Ss  = (__half*)smraw;                          // 32 x 1034 fp16
    float* Ks   = (float*)(smraw + SS_BYTES);              // 128 x 68 fp32
    float* rinv = (float*)(smraw + SS_BYTES + K_BYTES);    // 32
    float* Qs   = rinv + 32;                               // 32 x 68 fp32
    float* Vs0  = Ks;                                      // alias: V buf 0 (64 x 68)
    float* Vs1  = Ks + 64 * VSTR;                          // alias: V buf 1

    const int tid  = threadIdx.x;
    const int warp = tid >> 5;
    const int lane = tid & 31;
    const int bh   = blockIdx.x >> 5;
    const int row0 = (blockIdx.x & 31) * 32;
    const int b = bh / HEADS;
    const int h = bh % HEADS;

    const float* qbase = g_qkv + (size_t)(b * SEQ) * THREE_E + h * HDIM;
    const float* kbase = qbase + EMBED;
    const float* vbase = qbase + 2 * EMBED;

    // ---- load Q block 32x64 (fp32, conflict-free) ----
    #pragma unroll
    for (int it = 0; it < 2; it++){
        int idx = it * 256 + tid;
        int dc = idx & 15, r = idx >> 4;
        float4 v = *(const float4*)(qbase + (size_t)(row0 + r) * THREE_E + dc * 4);
        *(float4*)&Qs[r * QSTR + dc * 4] = v;
    }
    __syncthreads();

    // =========== pass 1: S = floor(Q K^T / 8), exact fp32 ===========
    // warp = rows r0..r0+3, cols lane + 32*i (i<4) within 128-col tile
    const int r0 = warp * 4;

    #pragma unroll 1
    for (int kt = 0; kt < SEQ / 128; kt++){
        if (kt) __syncthreads();
        // load K tile 128 x 64 (m-major, conflict-free float4 STS)
        #pragma unroll
        for (int it = 0; it < 8; it++){
            int idx = it * 256 + tid;
            int m = idx >> 4, dc = idx & 15;
            float4 v = *(const float4*)(kbase + (size_t)(kt * 128 + m) * THREE_E + dc * 4);
            *(float4*)&Ks[m * KSTR + dc * 4] = v;
        }
        __syncthreads();

        unsigned long long acc[4][4];
        #pragma unroll
        for (int r = 0; r < 4; r++)
            #pragma unroll
            for (int i = 0; i < 4; i++) acc[r][i] = 0ull;

        #pragma unroll
        for (int dg = 0; dg < 16; dg++){
            ulonglong2 q[4];
            #pragma unroll
            for (int r = 0; r < 4; r++)
                q[r] = *(const ulonglong2*)&Qs[(r0 + r) * QSTR + dg * 4];  // broadcast
            #pragma unroll
            for (int i = 0; i < 4; i++){
                ulonglong2 kv = *(const ulonglong2*)&Ks[(lane + 32 * i) * KSTR + dg * 4];
                #pragma unroll
                for (int r = 0; r < 4; r++){
                    fma2(acc[r][i], q[r].x, kv.x);
                    fma2(acc[r][i], q[r].y, kv.y);
                }
            }
        }

        // horizontal add + floor + fp16 store (integer-valued -> exact)
        #pragma unroll
        for (int r = 0; r < 4; r++){
            __half* srow = Ss + (r0 + r) * SSTR2 + kt * 128 + lane;
            #pragma unroll
            for (int i = 0; i < 4; i++){
                float2 t = up2(acc[r][i]);
                srow[32 * i] = __float2half_rn(floorf((t.x + t.y) * 0.125f));
            }
        }
    }
    __syncthreads();   // all warps done reading Ks before V overwrites it

    // ---- prefetch V tile 0 ----
    float4 vp[4];
    #pragma unroll
    for (int it = 0; it < 4; it++){
        int idx = it * 256 + tid;
        int m = idx >> 4, dc = idx & 15;
        vp[it] = *(const float4*)(vbase + (size_t)m * THREE_E + dc * 4);
    }

    // =========== softmax (fp16 strip; sum from quantized weights) ===========
    #pragma unroll
    for (int rr = 0; rr < 4; rr++){
        int r = warp * 4 + rr;
        __half2* row2 = (__half2*)(Ss + r * SSTR2);   // SSTR2 even -> aligned
        float mx = -1e30f;
        #pragma unroll
        for (int i = 0; i < 16; i++){
            float2 f = __half22float2(row2[lane + i * 32]);
            mx = fmaxf(mx, fmaxf(f.x, f.y));
        }
        #pragma unroll
        for (int o = 16; o > 0; o >>= 1) mx = fmaxf(mx, __shfl_xor_sync(0xffffffffu, mx, o));
        float sum = 0.f;
        #pragma unroll
        for (int i = 0; i < 16; i++){
            float2 f = __half22float2(row2[lane + i * 32]);
            __half2 e2 = __floats2half2_rn(__expf(f.x - mx), __expf(f.y - mx));
            row2[lane + i * 32] = e2;
            float2 q = __half22float2(e2);    // sum the QUANTIZED weights
            sum += q.x + q.y;
        }
        #pragma unroll
        for (int o = 16; o > 0; o >>= 1) sum += __shfl_xor_sync(0xffffffffu, sum, o);
        if (lane == 0) rinv[r] = 1.0f / sum;
    }

    // ---- prime pass 2: STS V tile 0 -> Vs0, prefetch tile 1 ----
    #pragma unroll
    for (int it = 0; it < 4; it++){
        int idx = it * 256 + tid;
        int m = idx >> 4, dc = idx & 15;
        float4 v = vp[it];
        v.x = tf32r(v.x); v.y = tf32r(v.y); v.z = tf32r(v.z); v.w = tf32r(v.w);
        *(float4*)&Vs0[m * VSTR + dc * 4] = v;
    }
    #pragma unroll
    for (int it = 0; it < 4; it++){
        int idx = it * 256 + tid;
        int m = idx >> 4, dc = idx & 15;
        vp[it] = *(const float4*)(vbase + (size_t)(64 + m) * THREE_E + dc * 4);
    }
    __syncthreads();   // Vs0 ready; softmax stores + rinv visible

    // =========== pass 2: C = E @ V via tf32 mma (double-buffered V) ===========
    const int mtile = warp & 1;
    const int nt0   = (warp >> 1) * 2;
    float C0[4] = {0.f,0.f,0.f,0.f}, C1[4] = {0.f,0.f,0.f,0.f};

    // A-frag scalar sources: rows (mtile*16 + lane>>2) and +8, col lane&3
    const __half* eA0 = Ss + (mtile * 16 + (lane >> 2)) * SSTR2 + (lane & 3);
    const __half* eA1 = eA0 + 8 * SSTR2;
    const int bm_ = lane & 3;
    const int bd_ = lane >> 2;
    const int v_off = bm_ * VSTR + nt0 * 8 + bd_;

    #pragma unroll 1
    for (int kt = 0; kt < 16; kt++){
        const float* cur = (kt & 1) ? Vs1 : Vs0;
        const float* vs_b0 = cur + v_off;

        #pragma unroll
        for (int ks = 0; ks < 8; ks++){
            const int eo = kt * 64 + ks * 8;
            uint32_t ea[4];
            ea[0] = __float_as_uint(__half2float(eA0[eo]));
            ea[1] = __float_as_uint(__half2float(eA1[eo]));
            ea[2] = __float_as_uint(__half2float(eA0[eo + 4]));
            ea[3] = __float_as_uint(__half2float(eA1[eo + 4]));
            const float* vrow0 = vs_b0 + (8 * ks) * VSTR;
            const float* vrow1 = vrow0 + 4 * VSTR;
            uint32_t b0[2], b1[2];
            b0[0] = __float_as_uint(vrow0[0]);
            b0[1] = __float_as_uint(vrow1[0]);
            b1[0] = __float_as_uint(vrow0[8]);
            b1[1] = __float_as_uint(vrow1[8]);
            mma_tf32(C0, ea, b0);
            mma_tf32(C1, ea, b1);
        }

        if (kt < 15){
            float* nxt = (kt & 1) ? Vs0 : Vs1;
            #pragma unroll
            for (int it = 0; it < 4; it++){
                int idx = it * 256 + tid;
                int m = idx >> 4, dc = idx & 15;
                float4 v = vp[it];
                v.x = tf32r(v.x); v.y = tf32r(v.y); v.z = tf32r(v.z); v.w = tf32r(v.w);
                *(float4*)&nxt[m * VSTR + dc * 4] = v;
            }
            if (kt < 14){
                #pragma unroll
                for (int it = 0; it < 4; it++){
                    int idx = it * 256 + tid;
                    int m = idx >> 4, dc = idx & 15;
                    vp[it] = *(const float4*)(vbase + (size_t)((kt + 2) * 64 + m) * THREE_E + dc * 4);
                }
            }
        }
        __syncthreads();
    }

    // ---- epilogue ----
    {
        const int er0 = mtile * 16 + (lane >> 2);
        const int d0  = nt0 * 8 + 2 * (lane & 3);
        float i0 = rinv[er0], i1 = rinv[er0 + 8];
        float* op0 = out + (size_t)(bh * SEQ + row0 + er0) * HDIM + d0;
        float* op1 = op0 + 8 * HDIM;
        *(float2*)op0       = make_float2(C0[0] * i0, C0[1] * i0);
        *(float2*)(op0 + 8) = make_float2(C1[0] * i0, C1[1] * i0);
        *(float2*)op1       = make_float2(C0[2] * i1, C0[3] * i1);
        *(float2*)(op1 + 8) = make_float2(C1[2] * i1, C1[3] * i1);
    }
}

// ============================================================
// launch
// ============================================================
extern "C" void kernel_launch(void* const* d_in, const int* in_sizes, int n_in,
                              void* d_out, int out_size) {
    const float* x    = (const float*)d_in[0];   // [8,1024,768]
    const float* Wqkv = (const float*)d_in[1];   // [2304,768]
    const float* bqkv = (const float*)d_in[2];   // [2304]
    float* out = (float*)d_out;                  // [8,12,1024,64]

    cudaFuncSetAttribute(attn_kernel, cudaFuncAttributeMaxDynamicSharedMemorySize, ATTN_SMEM);

    dim3 g1(THREE_E / 128, TOKENS / 128);
    qkv_gemm<<<g1, 256>>>(x, Wqkv, bqkv);

    attn_kernel<<<BATCH * HEADS * (SEQ / 32), 256, ATTN_SMEM>>>(out);
}